// round 4
// baseline (speedup 1.0000x reference)
#include <cuda_runtime.h>
#include <mma.h>
#include <cstddef>

using namespace nvcuda;

// Problem constants
#define N_NODES 50000
#define K_NB    32
#define D_IN    512
#define D_HID   128
#define D_OUT   64

#define M_PAD   50048   // 391 * 128, so the wmma GEMM can store unguarded

// Scratch (device globals: allocation-free, graph-capturable)
__device__ float g_h [(size_t)M_PAD   * D_HID];   // feat@W1 (no bias)
__device__ float g_h1[(size_t)N_NODES * D_HID];   // relu(median + b1)
__device__ float g_g [(size_t)N_NODES * D_OUT];   // h1@W2 (no bias)

// ---------------------------------------------------------------------------
// tf32 helpers
// ---------------------------------------------------------------------------
__device__ __forceinline__ float to_tf32(float x) {
    float r;
    asm("cvt.rna.tf32.f32 %0, %1;" : "=f"(r) : "f"(x));
    return r;
}

// ---------------------------------------------------------------------------
// GEMM1: C[M,128] = A[M,512] @ B[512,128], split-tf32 (hi*hi + hi*lo + lo*hi)
// Block: 128x128 tile, 256 threads (8 warps, 4x2 warp grid, 32x64 per warp).
// ---------------------------------------------------------------------------
#define LDA 20    // 16 + 4 pad (multiple of 4 -> 16B aligned rows)
#define LDB 132   // 128 + 4 pad

__global__ __launch_bounds__(256)
void gemm1_tf32(const float* __restrict__ A, const float* __restrict__ B,
                float* __restrict__ C, int M) {
    __shared__ float As_hi[128 * LDA], As_lo[128 * LDA];
    __shared__ float Bs_hi[16 * LDB],  Bs_lo[16 * LDB];

    const int tid    = threadIdx.x;
    const int wid    = tid >> 5;
    const int warp_m = wid >> 1;          // 0..3 -> 32 rows
    const int warp_n = wid & 1;           // 0..1 -> 64 cols
    const int row0   = blockIdx.x * 128;

    wmma::fragment<wmma::accumulator, 16, 16, 8, float> acc[2][4];
#pragma unroll
    for (int i = 0; i < 2; ++i)
#pragma unroll
        for (int j = 0; j < 4; ++j) wmma::fill_fragment(acc[i][j], 0.0f);

    for (int k0 = 0; k0 < D_IN; k0 += 16) {
        // Load A tile (128x16), split into tf32 hi/lo
        {
            int r  = tid >> 2;
            int c4 = (tid & 3) * 4;
#pragma unroll
            for (int p = 0; p < 2; ++p, r += 64) {
                float4 v = make_float4(0.f, 0.f, 0.f, 0.f);
                if (row0 + r < M)
                    v = *(const float4*)&A[(size_t)(row0 + r) * D_IN + k0 + c4];
                float4 hi, lo;
                hi.x = to_tf32(v.x); lo.x = to_tf32(v.x - hi.x);
                hi.y = to_tf32(v.y); lo.y = to_tf32(v.y - hi.y);
                hi.z = to_tf32(v.z); lo.z = to_tf32(v.z - hi.z);
                hi.w = to_tf32(v.w); lo.w = to_tf32(v.w - hi.w);
                *(float4*)&As_hi[r * LDA + c4] = hi;
                *(float4*)&As_lo[r * LDA + c4] = lo;
            }
        }
        // Load B tile (16x128), split into tf32 hi/lo
        {
            int r  = tid >> 5;
            int c4 = (tid & 31) * 4;
#pragma unroll
            for (int p = 0; p < 2; ++p, r += 8) {
                float4 v = *(const float4*)&B[(size_t)(k0 + r) * D_HID + c4];
                float4 hi, lo;
                hi.x = to_tf32(v.x); lo.x = to_tf32(v.x - hi.x);
                hi.y = to_tf32(v.y); lo.y = to_tf32(v.y - hi.y);
                hi.z = to_tf32(v.z); lo.z = to_tf32(v.z - hi.z);
                hi.w = to_tf32(v.w); lo.w = to_tf32(v.w - hi.w);
                *(float4*)&Bs_hi[r * LDB + c4] = hi;
                *(float4*)&Bs_lo[r * LDB + c4] = lo;
            }
        }
        __syncthreads();

#pragma unroll
        for (int kk = 0; kk < 2; ++kk) {
            wmma::fragment<wmma::matrix_b, 16, 16, 8,
                           wmma::precision::tf32, wmma::row_major> bh[4], bl[4];
#pragma unroll
            for (int j = 0; j < 4; ++j) {
                wmma::load_matrix_sync(bh[j], &Bs_hi[kk * 8 * LDB + warp_n * 64 + j * 16], LDB);
                wmma::load_matrix_sync(bl[j], &Bs_lo[kk * 8 * LDB + warp_n * 64 + j * 16], LDB);
            }
#pragma unroll
            for (int i = 0; i < 2; ++i) {
                wmma::fragment<wmma::matrix_a, 16, 16, 8,
                               wmma::precision::tf32, wmma::row_major> ah, al;
                wmma::load_matrix_sync(ah, &As_hi[(warp_m * 32 + i * 16) * LDA + kk * 8], LDA);
                wmma::load_matrix_sync(al, &As_lo[(warp_m * 32 + i * 16) * LDA + kk * 8], LDA);
#pragma unroll
                for (int j = 0; j < 4; ++j) {
                    wmma::mma_sync(acc[i][j], ah, bh[j], acc[i][j]);
                    wmma::mma_sync(acc[i][j], ah, bl[j], acc[i][j]);
                    wmma::mma_sync(acc[i][j], al, bh[j], acc[i][j]);
                }
            }
        }
        __syncthreads();
    }

    // Store (C buffer is padded to M_PAD rows -> no guard needed)
#pragma unroll
    for (int i = 0; i < 2; ++i)
#pragma unroll
        for (int j = 0; j < 4; ++j) {
            int r = row0 + warp_m * 32 + i * 16;
            int c = warp_n * 64 + j * 16;
            wmma::store_matrix_sync(&C[(size_t)r * D_HID + c], acc[i][j],
                                    D_HID, wmma::mem_row_major);
        }
}

// ---------------------------------------------------------------------------
// FFMA GEMM (layer 2, small): C[M,N] = A[M,K] @ B[K,N]   (no bias)
// ---------------------------------------------------------------------------
template<int BM, int BN, int BK, int TM, int TN>
__global__ __launch_bounds__((BM/TM)*(BN/TN))
void gemm_ffma(const float* __restrict__ A, const float* __restrict__ B,
               float* __restrict__ C, int M, int N, int K) {
    constexpr int NT = (BM / TM) * (BN / TN);
    __shared__ float As[BK * BM];
    __shared__ float Bs[BK * BN];

    const int tid  = threadIdx.x;
    const int row0 = blockIdx.x * BM;
    const int tr   = tid / (BN / TN);
    const int tc   = tid % (BN / TN);

    float acc[TM][TN];
#pragma unroll
    for (int m = 0; m < TM; ++m)
#pragma unroll
        for (int n = 0; n < TN; ++n) acc[m][n] = 0.0f;

    for (int k0 = 0; k0 < K; k0 += BK) {
        for (int i = tid; i < BM * BK / 4; i += NT) {
            int r  = i / (BK / 4);
            int c4 = i % (BK / 4);
            int grow = row0 + r;
            float4 val = make_float4(0.f, 0.f, 0.f, 0.f);
            if (grow < M)
                val = *(const float4*)&A[(size_t)grow * K + k0 + c4 * 4];
            As[(c4 * 4 + 0) * BM + r] = val.x;
            As[(c4 * 4 + 1) * BM + r] = val.y;
            As[(c4 * 4 + 2) * BM + r] = val.z;
            As[(c4 * 4 + 3) * BM + r] = val.w;
        }
        for (int i = tid; i < BK * BN / 4; i += NT) {
            int r  = i / (BN / 4);
            int c4 = i % (BN / 4);
            *(float4*)&Bs[r * BN + c4 * 4] =
                *(const float4*)&B[(size_t)(k0 + r) * N + c4 * 4];
        }
        __syncthreads();

#pragma unroll
        for (int k = 0; k < BK; ++k) {
            float a[TM], b[TN];
#pragma unroll
            for (int m = 0; m < TM; ++m) a[m] = As[k * BM + tr * TM + m];
#pragma unroll
            for (int n = 0; n < TN; ++n) b[n] = Bs[k * BN + tc * TN + n];
#pragma unroll
            for (int m = 0; m < TM; ++m)
#pragma unroll
                for (int n = 0; n < TN; ++n)
                    acc[m][n] = fmaf(a[m], b[n], acc[m][n]);
        }
        __syncthreads();
    }

#pragma unroll
    for (int m = 0; m < TM; ++m) {
        int grow = row0 + tr * TM + m;
        if (grow < M) {
#pragma unroll
            for (int n = 0; n < TN; ++n)
                C[(size_t)grow * N + tc * TN + n] = acc[m][n];
        }
    }
}

// ---------------------------------------------------------------------------
// Batcher odd-even merge sort (ascending), fully unrolled via templates.
// 63 comparators for n=16 (vs 80 for bitonic).
// ---------------------------------------------------------------------------
template<int I, int J>
__device__ __forceinline__ void cmpswap(float* v) {
    float a = v[I], b = v[J];
    v[I] = fminf(a, b);
    v[J] = fmaxf(a, b);
}

template<int I, int END, int STEP, int R>
__device__ __forceinline__ void oem_cloop(float* v) {
    if constexpr (I + R < END) {
        cmpswap<I, I + R>(v);
        oem_cloop<I + STEP, END, STEP, R>(v);
    }
}

template<int LO, int N, int R>
__device__ __forceinline__ void oem_merge(float* v) {
    constexpr int M = R * 2;
    if constexpr (M < N) {
        oem_merge<LO, N, M>(v);
        oem_merge<LO + R, N, M>(v);
        oem_cloop<LO + R, LO + N, M, R>(v);
    } else {
        cmpswap<LO, LO + R>(v);
    }
}

template<int LO, int N>
__device__ __forceinline__ void oem_sort(float* v) {
    if constexpr (N > 1) {
        constexpr int M = N / 2;
        oem_sort<LO, M>(v);
        oem_sort<LO + M, M>(v);
        oem_merge<LO, N, 1>(v);
    }
}

// Lower median (rank 15, 0-indexed) of 32: sort both 16-halves ascending,
// then bitonic-halver: max_i min(v[i], v[31-i]) is exactly the 16th smallest.
__device__ __forceinline__ float median32(float* v) {
    oem_sort<0, 16>(v);
    oem_sort<0, 16>(v + 16);
    float med = fminf(v[0], v[31]);
#pragma unroll
    for (int i = 1; i < 16; ++i)
        med = fmaxf(med, fminf(v[i], v[31 - i]));
    return med;
}

// ---------------------------------------------------------------------------
// Layer-1 median + bias + ReLU: one block per node, 128 threads.
// ---------------------------------------------------------------------------
__global__ __launch_bounds__(D_HID)
void median_relu_128(const int* __restrict__ nb, const float* __restrict__ bias) {
    const int n = blockIdx.x;
    const int d = threadIdx.x;

    __shared__ int sidx[K_NB];
    if (d < K_NB) sidx[d] = nb[(size_t)n * K_NB + d];
    __syncthreads();

    float v[K_NB];
#pragma unroll
    for (int k = 0; k < K_NB; ++k)
        v[k] = __ldg(&g_h[(size_t)sidx[k] * D_HID + d]);

    float med = median32(v) + bias[d];
    g_h1[(size_t)n * D_HID + d] = fmaxf(med, 0.0f);
}

// ---------------------------------------------------------------------------
// Layer-2 median + bias: 2 nodes per block (128 threads), 64 features each.
// ---------------------------------------------------------------------------
__global__ __launch_bounds__(128)
void median_64(const int* __restrict__ nb, const float* __restrict__ bias,
               float* __restrict__ out) {
    const int local = threadIdx.x >> 6;
    const int n = blockIdx.x * 2 + local;
    const int d = threadIdx.x & 63;

    __shared__ int sidx[2 * K_NB];
    if (threadIdx.x < 2 * K_NB)
        sidx[threadIdx.x] = nb[(size_t)(blockIdx.x * 2) * K_NB + threadIdx.x];
    __syncthreads();

    float v[K_NB];
#pragma unroll
    for (int k = 0; k < K_NB; ++k)
        v[k] = __ldg(&g_g[(size_t)sidx[local * K_NB + k] * D_OUT + d]);

    out[(size_t)n * D_OUT + d] = median32(v) + bias[d];
}

// ---------------------------------------------------------------------------
extern "C" void kernel_launch(void* const* d_in, const int* in_sizes, int n_in,
                              void* d_out, int out_size) {
    const float* feat = (const float*)d_in[0];
    const float* W1   = (const float*)d_in[1];
    const float* b1   = (const float*)d_in[2];
    const float* W2   = (const float*)d_in[3];
    const float* b2   = (const float*)d_in[4];
    const int*   nb   = (const int*)d_in[5];
    float* out = (float*)d_out;

    void *ph = nullptr, *ph1 = nullptr, *pg = nullptr;
    cudaGetSymbolAddress(&ph,  g_h);
    cudaGetSymbolAddress(&ph1, g_h1);
    cudaGetSymbolAddress(&pg,  g_g);
    float* h  = (float*)ph;
    float* h1 = (float*)ph1;
    float* g  = (float*)pg;

    // 1) h = feat @ W1   [50000,512] x [512,128]  (split-tf32 tensor cores)
    gemm1_tf32<<<M_PAD / 128, 256>>>(feat, W1, h, N_NODES);

    // 2) h1 = relu(median_k h[nb] + b1)
    median_relu_128<<<N_NODES, D_HID>>>(nb, b1);

    // 3) g = h1 @ W2   [50000,128] x [128,64]
    {
        constexpr int BM = 128, BN = 64, BK = 16, TM = 8, TN = 8;
        dim3 grid((N_NODES + BM - 1) / BM);
        gemm_ffma<BM, BN, BK, TM, TN>
            <<<grid, (BM / TM) * (BN / TN)>>>(h1, W2, g, N_NODES, D_OUT, D_HID);
    }

    // 4) out = median_k g[nb] + b2
    median_64<<<N_NODES / 2, 128>>>(nb, b2, out);
}

// round 5
// speedup vs baseline: 1.5170x; 1.5170x over previous
#include <cuda_runtime.h>
#include <cuda_bf16.h>
#include <mma.h>
#include <cstddef>

using namespace nvcuda;

// Problem constants
#define N_NODES 50000
#define K_NB    32
#define D_IN    512
#define D_HID   128
#define D_OUT   64

#define M_PAD   50048   // 391 * 128: wmma GEMM stores unguarded

// Scratch (device globals: allocation-free, graph-capturable)
__device__ float g_h [(size_t)M_PAD   * D_HID];   // feat@W1 (no bias)
__device__ float g_h1[(size_t)N_NODES * D_HID];   // relu(median + b1)
__device__ float g_g [(size_t)N_NODES * D_OUT];   // h1@W2 (no bias)

// ---------------------------------------------------------------------------
// GEMM1: C[M,128] = A[M,512] @ B[512,128], bf16 split (hi*hi + hi*lo + lo*hi)
// Block: 128x128 tile, 256 threads (8 warps, 4x2 grid, 32x64 per warp), BK=32.
// ---------------------------------------------------------------------------
#define BK1   32
#define LDA_B (BK1 + 8)    // 40 bf16 = 80 B row stride  (LDSM conflict-free)
#define LDB_B (128 + 8)    // 136 bf16 = 272 B row stride (LDSM conflict-free)

__device__ __forceinline__ void split_bf16(float x, __nv_bfloat16& hi, __nv_bfloat16& lo) {
    hi = __float2bfloat16_rn(x);
    lo = __float2bfloat16_rn(x - __bfloat162float(hi));
}

__global__ __launch_bounds__(256)
void gemm1_bf16(const float* __restrict__ A, const float* __restrict__ B,
                float* __restrict__ C, int M) {
    __shared__ __nv_bfloat16 As_hi[128 * LDA_B], As_lo[128 * LDA_B];
    __shared__ __nv_bfloat16 Bs_hi[BK1 * LDB_B], Bs_lo[BK1 * LDB_B];

    const int tid    = threadIdx.x;
    const int wid    = tid >> 5;
    const int warp_m = wid >> 1;          // 0..3 -> 32-row strip
    const int warp_n = wid & 1;           // 0..1 -> 64-col strip
    const int row0   = blockIdx.x * 128;

    wmma::fragment<wmma::accumulator, 16, 16, 16, float> acc[2][4];
#pragma unroll
    for (int i = 0; i < 2; ++i)
#pragma unroll
        for (int j = 0; j < 4; ++j) wmma::fill_fragment(acc[i][j], 0.0f);

    for (int k0 = 0; k0 < D_IN; k0 += BK1) {
        // ---- A tile: 128 x 32 fp32 -> bf16 hi/lo. 8 thr/row, 32 rows/pass.
        {
            int r  = tid >> 3;
            int c4 = (tid & 7) * 4;
#pragma unroll
            for (int p = 0; p < 4; ++p) {
                int row = r + p * 32;
                float4 v = make_float4(0.f, 0.f, 0.f, 0.f);
                if (row0 + row < M)
                    v = *(const float4*)&A[(size_t)(row0 + row) * D_IN + k0 + c4];
                __nv_bfloat16 h0,h1,h2,h3, l0,l1,l2,l3;
                split_bf16(v.x, h0, l0); split_bf16(v.y, h1, l1);
                split_bf16(v.z, h2, l2); split_bf16(v.w, h3, l3);
                int o = row * LDA_B + c4;
                *(__nv_bfloat162*)&As_hi[o]     = __nv_bfloat162(h0, h1);
                *(__nv_bfloat162*)&As_hi[o + 2] = __nv_bfloat162(h2, h3);
                *(__nv_bfloat162*)&As_lo[o]     = __nv_bfloat162(l0, l1);
                *(__nv_bfloat162*)&As_lo[o + 2] = __nv_bfloat162(l2, l3);
            }
        }
        // ---- B tile: 32 x 128 fp32 -> bf16 hi/lo. 32 thr/row, 8 rows/pass.
        {
            int r  = tid >> 5;
            int c4 = (tid & 31) * 4;
#pragma unroll
            for (int p = 0; p < 4; ++p) {
                int row = r + p * 8;
                float4 v = *(const float4*)&B[(size_t)(k0 + row) * D_HID + c4];
                __nv_bfloat16 h0,h1,h2,h3, l0,l1,l2,l3;
                split_bf16(v.x, h0, l0); split_bf16(v.y, h1, l1);
                split_bf16(v.z, h2, l2); split_bf16(v.w, h3, l3);
                int o = row * LDB_B + c4;
                *(__nv_bfloat162*)&Bs_hi[o]     = __nv_bfloat162(h0, h1);
                *(__nv_bfloat162*)&Bs_hi[o + 2] = __nv_bfloat162(h2, h3);
                *(__nv_bfloat162*)&Bs_lo[o]     = __nv_bfloat162(l0, l1);
                *(__nv_bfloat162*)&Bs_lo[o + 2] = __nv_bfloat162(l2, l3);
            }
        }
        __syncthreads();

#pragma unroll
        for (int kk = 0; kk < 2; ++kk) {
            wmma::fragment<wmma::matrix_b, 16, 16, 16,
                           __nv_bfloat16, wmma::row_major> bh[4], bl[4];
#pragma unroll
            for (int j = 0; j < 4; ++j) {
                wmma::load_matrix_sync(bh[j], &Bs_hi[(kk * 16) * LDB_B + warp_n * 64 + j * 16], LDB_B);
                wmma::load_matrix_sync(bl[j], &Bs_lo[(kk * 16) * LDB_B + warp_n * 64 + j * 16], LDB_B);
            }
#pragma unroll
            for (int i = 0; i < 2; ++i) {
                wmma::fragment<wmma::matrix_a, 16, 16, 16,
                               __nv_bfloat16, wmma::row_major> ah, al;
                wmma::load_matrix_sync(ah, &As_hi[(warp_m * 32 + i * 16) * LDA_B + kk * 16], LDA_B);
                wmma::load_matrix_sync(al, &As_lo[(warp_m * 32 + i * 16) * LDA_B + kk * 16], LDA_B);
#pragma unroll
                for (int j = 0; j < 4; ++j) {
                    wmma::mma_sync(acc[i][j], ah, bh[j], acc[i][j]);
                    wmma::mma_sync(acc[i][j], ah, bl[j], acc[i][j]);
                    wmma::mma_sync(acc[i][j], al, bh[j], acc[i][j]);
                }
            }
        }
        __syncthreads();
    }

    // Store (C padded to M_PAD rows -> unguarded)
#pragma unroll
    for (int i = 0; i < 2; ++i)
#pragma unroll
        for (int j = 0; j < 4; ++j) {
            int r = row0 + warp_m * 32 + i * 16;
            int c = warp_n * 64 + j * 16;
            wmma::store_matrix_sync(&C[(size_t)r * D_HID + c], acc[i][j],
                                    D_HID, wmma::mem_row_major);
        }
}

// ---------------------------------------------------------------------------
// FFMA GEMM (layer 2, small): C[M,N] = A[M,K] @ B[K,N]   (no bias)
// ---------------------------------------------------------------------------
template<int BM, int BN, int BK, int TM, int TN>
__global__ __launch_bounds__((BM/TM)*(BN/TN))
void gemm_ffma(const float* __restrict__ A, const float* __restrict__ B,
               float* __restrict__ C, int M, int N, int K) {
    constexpr int NT = (BM / TM) * (BN / TN);
    __shared__ float As[BK * BM];
    __shared__ float Bs[BK * BN];

    const int tid  = threadIdx.x;
    const int row0 = blockIdx.x * BM;
    const int tr   = tid / (BN / TN);
    const int tc   = tid % (BN / TN);

    float acc[TM][TN];
#pragma unroll
    for (int m = 0; m < TM; ++m)
#pragma unroll
        for (int n = 0; n < TN; ++n) acc[m][n] = 0.0f;

    for (int k0 = 0; k0 < K; k0 += BK) {
        for (int i = tid; i < BM * BK / 4; i += NT) {
            int r  = i / (BK / 4);
            int c4 = i % (BK / 4);
            int grow = row0 + r;
            float4 val = make_float4(0.f, 0.f, 0.f, 0.f);
            if (grow < M)
                val = *(const float4*)&A[(size_t)grow * K + k0 + c4 * 4];
            As[(c4 * 4 + 0) * BM + r] = val.x;
            As[(c4 * 4 + 1) * BM + r] = val.y;
            As[(c4 * 4 + 2) * BM + r] = val.z;
            As[(c4 * 4 + 3) * BM + r] = val.w;
        }
        for (int i = tid; i < BK * BN / 4; i += NT) {
            int r  = i / (BN / 4);
            int c4 = i % (BN / 4);
            *(float4*)&Bs[r * BN + c4 * 4] =
                *(const float4*)&B[(size_t)(k0 + r) * N + c4 * 4];
        }
        __syncthreads();

#pragma unroll
        for (int k = 0; k < BK; ++k) {
            float a[TM], b[TN];
#pragma unroll
            for (int m = 0; m < TM; ++m) a[m] = As[k * BM + tr * TM + m];
#pragma unroll
            for (int n = 0; n < TN; ++n) b[n] = Bs[k * BN + tc * TN + n];
#pragma unroll
            for (int m = 0; m < TM; ++m)
#pragma unroll
                for (int n = 0; n < TN; ++n)
                    acc[m][n] = fmaf(a[m], b[n], acc[m][n]);
        }
        __syncthreads();
    }

#pragma unroll
    for (int m = 0; m < TM; ++m) {
        int grow = row0 + tr * TM + m;
        if (grow < M) {
#pragma unroll
            for (int n = 0; n < TN; ++n)
                C[(size_t)grow * N + tc * TN + n] = acc[m][n];
        }
    }
}

// ---------------------------------------------------------------------------
// Batcher odd-even merge sort (ascending), fully unrolled via templates.
// ---------------------------------------------------------------------------
template<int I, int J>
__device__ __forceinline__ void cmpswap(float* v) {
    float a = v[I], b = v[J];
    v[I] = fminf(a, b);
    v[J] = fmaxf(a, b);
}

template<int I, int END, int STEP, int R>
__device__ __forceinline__ void oem_cloop(float* v) {
    if constexpr (I + R < END) {
        cmpswap<I, I + R>(v);
        oem_cloop<I + STEP, END, STEP, R>(v);
    }
}

template<int LO, int N, int R>
__device__ __forceinline__ void oem_merge(float* v) {
    constexpr int M = R * 2;
    if constexpr (M < N) {
        oem_merge<LO, N, M>(v);
        oem_merge<LO + R, N, M>(v);
        oem_cloop<LO + R, LO + N, M, R>(v);
    } else {
        cmpswap<LO, LO + R>(v);
    }
}

template<int LO, int N>
__device__ __forceinline__ void oem_sort(float* v) {
    if constexpr (N > 1) {
        constexpr int M = N / 2;
        oem_sort<LO, M>(v);
        oem_sort<LO + M, M>(v);
        oem_merge<LO, N, 1>(v);
    }
}

// Lower median (rank 15, 0-indexed) of 32: sort both 16-halves ascending,
// then bitonic-halver: max_i min(v[i], v[31-i]) is exactly the 16th smallest.
__device__ __forceinline__ float median32(float* v) {
    oem_sort<0, 16>(v);
    oem_sort<0, 16>(v + 16);
    float med = fminf(v[0], v[31]);
#pragma unroll
    for (int i = 1; i < 16; ++i)
        med = fmaxf(med, fminf(v[i], v[31 - i]));
    return med;
}

// ---------------------------------------------------------------------------
// Layer-1 median + bias + ReLU: one block per node, 128 threads.
// ---------------------------------------------------------------------------
__global__ __launch_bounds__(D_HID)
void median_relu_128(const int* __restrict__ nb, const float* __restrict__ bias) {
    const int n = blockIdx.x;
    const int d = threadIdx.x;

    __shared__ int sidx[K_NB];
    if (d < K_NB) sidx[d] = nb[(size_t)n * K_NB + d];
    __syncthreads();

    float v[K_NB];
#pragma unroll
    for (int k = 0; k < K_NB; ++k)
        v[k] = __ldg(&g_h[(size_t)sidx[k] * D_HID + d]);

    float med = median32(v) + bias[d];
    g_h1[(size_t)n * D_HID + d] = fmaxf(med, 0.0f);
}

// ---------------------------------------------------------------------------
// Layer-2 median + bias: 2 nodes per block (128 threads), 64 features each.
// ---------------------------------------------------------------------------
__global__ __launch_bounds__(128)
void median_64(const int* __restrict__ nb, const float* __restrict__ bias,
               float* __restrict__ out) {
    const int local = threadIdx.x >> 6;
    const int n = blockIdx.x * 2 + local;
    const int d = threadIdx.x & 63;

    __shared__ int sidx[2 * K_NB];
    if (threadIdx.x < 2 * K_NB)
        sidx[threadIdx.x] = nb[(size_t)(blockIdx.x * 2) * K_NB + threadIdx.x];
    __syncthreads();

    float v[K_NB];
#pragma unroll
    for (int k = 0; k < K_NB; ++k)
        v[k] = __ldg(&g_g[(size_t)sidx[local * K_NB + k] * D_OUT + d]);

    out[(size_t)n * D_OUT + d] = median32(v) + bias[d];
}

// ---------------------------------------------------------------------------
extern "C" void kernel_launch(void* const* d_in, const int* in_sizes, int n_in,
                              void* d_out, int out_size) {
    const float* feat = (const float*)d_in[0];
    const float* W1   = (const float*)d_in[1];
    const float* b1   = (const float*)d_in[2];
    const float* W2   = (const float*)d_in[3];
    const float* b2   = (const float*)d_in[4];
    const int*   nb   = (const int*)d_in[5];
    float* out = (float*)d_out;

    void *ph = nullptr, *ph1 = nullptr, *pg = nullptr;
    cudaGetSymbolAddress(&ph,  g_h);
    cudaGetSymbolAddress(&ph1, g_h1);
    cudaGetSymbolAddress(&pg,  g_g);
    float* h  = (float*)ph;
    float* h1 = (float*)ph1;
    float* g  = (float*)pg;

    // 1) h = feat @ W1   [50000,512] x [512,128]  (bf16-split tensor cores)
    gemm1_bf16<<<M_PAD / 128, 256>>>(feat, W1, h, N_NODES);

    // 2) h1 = relu(median_k h[nb] + b1)
    median_relu_128<<<N_NODES, D_HID>>>(nb, b1);

    // 3) g = h1 @ W2   [50000,128] x [128,64]
    {
        constexpr int BM = 128, BN = 64, BK = 16, TM = 8, TN = 8;
        dim3 grid((N_NODES + BM - 1) / BM);
        gemm_ffma<BM, BN, BK, TM, TN>
            <<<grid, (BM / TM) * (BN / TN)>>>(h1, W2, g, N_NODES, D_OUT, D_HID);
    }

    // 4) out = median_k g[nb] + b2
    median_64<<<N_NODES / 2, 128>>>(nb, b2, out);
}

// round 6
// speedup vs baseline: 1.6465x; 1.0854x over previous
#include <cuda_runtime.h>
#include <cuda_bf16.h>
#include <mma.h>
#include <cstddef>

using namespace nvcuda;

// Problem constants
#define N_NODES 50000
#define K_NB    32
#define D_IN    512
#define D_HID   128
#define D_OUT   64

#define M_PAD   50048   // 391 * 128: wmma GEMM stores unguarded

// Scratch (device globals: allocation-free, graph-capturable)
__device__ float g_h [(size_t)M_PAD   * D_HID];   // feat@W1 (no bias)
__device__ float g_h1[(size_t)N_NODES * D_HID];   // relu(median + b1)
__device__ float g_g [(size_t)N_NODES * D_OUT];   // h1@W2 (no bias)

// ---------------------------------------------------------------------------
// GEMM1: C[M,128] = A[M,512] @ B[512,128], bf16 split (hi*hi + hi*lo + lo*hi)
// 128x128 tile, 256 threads (8 warps, 4x2), BK=32, register-prefetch pipeline.
// ---------------------------------------------------------------------------
#define BK1   32
#define LDA_B (BK1 + 8)    // 40 bf16 row stride
#define LDB_B (128 + 8)    // 136 bf16 row stride

__device__ __forceinline__ void split_bf16(float x, __nv_bfloat16& hi, __nv_bfloat16& lo) {
    hi = __float2bfloat16_rn(x);
    lo = __float2bfloat16_rn(x - __bfloat162float(hi));
}

__device__ __forceinline__ void store_split4(__nv_bfloat16* hi_base, __nv_bfloat16* lo_base,
                                             int off, float4 v) {
    __nv_bfloat16 h0,h1,h2,h3, l0,l1,l2,l3;
    split_bf16(v.x, h0, l0); split_bf16(v.y, h1, l1);
    split_bf16(v.z, h2, l2); split_bf16(v.w, h3, l3);
    *(__nv_bfloat162*)&hi_base[off]     = __nv_bfloat162(h0, h1);
    *(__nv_bfloat162*)&hi_base[off + 2] = __nv_bfloat162(h2, h3);
    *(__nv_bfloat162*)&lo_base[off]     = __nv_bfloat162(l0, l1);
    *(__nv_bfloat162*)&lo_base[off + 2] = __nv_bfloat162(l2, l3);
}

__global__ __launch_bounds__(256)
void gemm1_bf16(const float* __restrict__ A, const float* __restrict__ B,
                float* __restrict__ C, int M) {
    __shared__ __nv_bfloat16 As_hi[128 * LDA_B], As_lo[128 * LDA_B];
    __shared__ __nv_bfloat16 Bs_hi[BK1 * LDB_B], Bs_lo[BK1 * LDB_B];

    const int tid    = threadIdx.x;
    const int wid    = tid >> 5;
    const int warp_m = wid >> 1;
    const int warp_n = wid & 1;
    const int row0   = blockIdx.x * 128;

    // Per-thread load coordinates
    const int ar  = tid >> 3;            // A: 8 thr/row, rows ar + p*32
    const int ac4 = (tid & 7) * 4;
    const int br  = tid >> 5;            // B: 32 thr/row, rows br + p*8
    const int bc4 = (tid & 31) * 4;

    wmma::fragment<wmma::accumulator, 16, 16, 16, float> acc[2][4];
#pragma unroll
    for (int i = 0; i < 2; ++i)
#pragma unroll
        for (int j = 0; j < 4; ++j) wmma::fill_fragment(acc[i][j], 0.0f);

    float4 pa[4], pb[4];

    // Prologue: load tile 0 into registers
#pragma unroll
    for (int p = 0; p < 4; ++p) {
        int row = ar + p * 32;
        pa[p] = make_float4(0.f, 0.f, 0.f, 0.f);
        if (row0 + row < M)
            pa[p] = *(const float4*)&A[(size_t)(row0 + row) * D_IN + ac4];
        pb[p] = *(const float4*)&B[(size_t)(br + p * 8) * D_HID + bc4];
    }

    for (int t = 0; t < D_IN / BK1; ++t) {
        // Store prefetched tile to smem
#pragma unroll
        for (int p = 0; p < 4; ++p) {
            store_split4(As_hi, As_lo, (ar + p * 32) * LDA_B + ac4, pa[p]);
            store_split4(Bs_hi, Bs_lo, (br + p * 8) * LDB_B + bc4, pb[p]);
        }
        __syncthreads();

        // Issue prefetch for next tile (hidden behind compute)
        if (t + 1 < D_IN / BK1) {
            int k0 = (t + 1) * BK1;
#pragma unroll
            for (int p = 0; p < 4; ++p) {
                int row = ar + p * 32;
                pa[p] = make_float4(0.f, 0.f, 0.f, 0.f);
                if (row0 + row < M)
                    pa[p] = *(const float4*)&A[(size_t)(row0 + row) * D_IN + k0 + ac4];
                pb[p] = *(const float4*)&B[(size_t)(k0 + br + p * 8) * D_HID + bc4];
            }
        }

        // Compute on current smem tile
#pragma unroll
        for (int kk = 0; kk < 2; ++kk) {
            wmma::fragment<wmma::matrix_b, 16, 16, 16,
                           __nv_bfloat16, wmma::row_major> bh[4], bl[4];
#pragma unroll
            for (int j = 0; j < 4; ++j) {
                wmma::load_matrix_sync(bh[j], &Bs_hi[(kk * 16) * LDB_B + warp_n * 64 + j * 16], LDB_B);
                wmma::load_matrix_sync(bl[j], &Bs_lo[(kk * 16) * LDB_B + warp_n * 64 + j * 16], LDB_B);
            }
#pragma unroll
            for (int i = 0; i < 2; ++i) {
                wmma::fragment<wmma::matrix_a, 16, 16, 16,
                               __nv_bfloat16, wmma::row_major> ah, al;
                wmma::load_matrix_sync(ah, &As_hi[(warp_m * 32 + i * 16) * LDA_B + kk * 16], LDA_B);
                wmma::load_matrix_sync(al, &As_lo[(warp_m * 32 + i * 16) * LDA_B + kk * 16], LDA_B);
#pragma unroll
                for (int j = 0; j < 4; ++j) {
                    wmma::mma_sync(acc[i][j], ah, bh[j], acc[i][j]);
                    wmma::mma_sync(acc[i][j], ah, bl[j], acc[i][j]);
                    wmma::mma_sync(acc[i][j], al, bh[j], acc[i][j]);
                }
            }
        }
        __syncthreads();
    }

#pragma unroll
    for (int i = 0; i < 2; ++i)
#pragma unroll
        for (int j = 0; j < 4; ++j) {
            int r = row0 + warp_m * 32 + i * 16;
            int c = warp_n * 64 + j * 16;
            wmma::store_matrix_sync(&C[(size_t)r * D_HID + c], acc[i][j],
                                    D_HID, wmma::mem_row_major);
        }
}

// ---------------------------------------------------------------------------
// FFMA GEMM (layer 2, small): C[M,N] = A[M,K] @ B[K,N]
// ---------------------------------------------------------------------------
template<int BM, int BN, int BK, int TM, int TN>
__global__ __launch_bounds__((BM/TM)*(BN/TN))
void gemm_ffma(const float* __restrict__ A, const float* __restrict__ B,
               float* __restrict__ C, int M, int N, int K) {
    constexpr int NT = (BM / TM) * (BN / TN);
    __shared__ float As[BK * BM];
    __shared__ float Bs[BK * BN];

    const int tid  = threadIdx.x;
    const int row0 = blockIdx.x * BM;
    const int tr   = tid / (BN / TN);
    const int tc   = tid % (BN / TN);

    float acc[TM][TN];
#pragma unroll
    for (int m = 0; m < TM; ++m)
#pragma unroll
        for (int n = 0; n < TN; ++n) acc[m][n] = 0.0f;

    for (int k0 = 0; k0 < K; k0 += BK) {
        for (int i = tid; i < BM * BK / 4; i += NT) {
            int r  = i / (BK / 4);
            int c4 = i % (BK / 4);
            int grow = row0 + r;
            float4 val = make_float4(0.f, 0.f, 0.f, 0.f);
            if (grow < M)
                val = *(const float4*)&A[(size_t)grow * K + k0 + c4 * 4];
            As[(c4 * 4 + 0) * BM + r] = val.x;
            As[(c4 * 4 + 1) * BM + r] = val.y;
            As[(c4 * 4 + 2) * BM + r] = val.z;
            As[(c4 * 4 + 3) * BM + r] = val.w;
        }
        for (int i = tid; i < BK * BN / 4; i += NT) {
            int r  = i / (BN / 4);
            int c4 = i % (BN / 4);
            *(float4*)&Bs[r * BN + c4 * 4] =
                *(const float4*)&B[(size_t)(k0 + r) * N + c4 * 4];
        }
        __syncthreads();

#pragma unroll
        for (int k = 0; k < BK; ++k) {
            float a[TM], b[TN];
#pragma unroll
            for (int m = 0; m < TM; ++m) a[m] = As[k * BM + tr * TM + m];
#pragma unroll
            for (int n = 0; n < TN; ++n) b[n] = Bs[k * BN + tc * TN + n];
#pragma unroll
            for (int m = 0; m < TM; ++m)
#pragma unroll
                for (int n = 0; n < TN; ++n)
                    acc[m][n] = fmaf(a[m], b[n], acc[m][n]);
        }
        __syncthreads();
    }

#pragma unroll
    for (int m = 0; m < TM; ++m) {
        int grow = row0 + tr * TM + m;
        if (grow < M) {
#pragma unroll
            for (int n = 0; n < TN; ++n)
                C[(size_t)grow * N + tc * TN + n] = acc[m][n];
        }
    }
}

// ---------------------------------------------------------------------------
// Batcher odd-even merge sort on float2 lanes (two independent medians).
// ---------------------------------------------------------------------------
template<int I, int J>
__device__ __forceinline__ void cmpswap2(float2* v) {
    float ax = v[I].x, bx = v[J].x;
    float ay = v[I].y, by = v[J].y;
    v[I].x = fminf(ax, bx); v[J].x = fmaxf(ax, bx);
    v[I].y = fminf(ay, by); v[J].y = fmaxf(ay, by);
}

template<int I, int END, int STEP, int R>
__device__ __forceinline__ void oem_cloop(float2* v) {
    if constexpr (I + R < END) {
        cmpswap2<I, I + R>(v);
        oem_cloop<I + STEP, END, STEP, R>(v);
    }
}

template<int LO, int N, int R>
__device__ __forceinline__ void oem_merge(float2* v) {
    constexpr int M = R * 2;
    if constexpr (M < N) {
        oem_merge<LO, N, M>(v);
        oem_merge<LO + R, N, M>(v);
        oem_cloop<LO + R, LO + N, M, R>(v);
    } else {
        cmpswap2<LO, LO + R>(v);
    }
}

template<int LO, int N>
__device__ __forceinline__ void oem_sort(float2* v) {
    if constexpr (N > 1) {
        constexpr int M = N / 2;
        oem_sort<LO, M>(v);
        oem_sort<LO + M, M>(v);
        oem_merge<LO, N, 1>(v);
    }
}

// Lower median (rank 15) of 32, on both float2 lanes.
__device__ __forceinline__ float2 median32_f2(float2* v) {
    oem_sort<0, 16>(v);
    oem_sort<0, 16>(v + 16);
    float mx = fminf(v[0].x, v[31].x);
    float my = fminf(v[0].y, v[31].y);
#pragma unroll
    for (int i = 1; i < 16; ++i) {
        mx = fmaxf(mx, fminf(v[i].x, v[31 - i].x));
        my = fmaxf(my, fminf(v[i].y, v[31 - i].y));
    }
    return make_float2(mx, my);
}

// ---------------------------------------------------------------------------
// Layer-1 median + bias + ReLU: 2 nodes/block, 64 threads/node, 2 feat/thread.
// ---------------------------------------------------------------------------
__global__ __launch_bounds__(128)
void median_relu_f2(const int* __restrict__ nb, const float* __restrict__ bias) {
    const int local = threadIdx.x >> 6;               // node within block
    const int n  = blockIdx.x * 2 + local;
    const int d2 = threadIdx.x & 63;                  // float2 feature index

    __shared__ int sidx[2 * K_NB];
    if (threadIdx.x < 2 * K_NB)
        sidx[threadIdx.x] = nb[(size_t)(blockIdx.x * 2) * K_NB + threadIdx.x];
    __syncthreads();

    const float2* hp = (const float2*)g_h;
    float2 v[K_NB];
#pragma unroll
    for (int k = 0; k < K_NB; ++k)
        v[k] = __ldg(&hp[(size_t)sidx[local * K_NB + k] * (D_HID / 2) + d2]);

    float2 med = median32_f2(v);
    float2 b = ((const float2*)bias)[d2];
    float2 r = make_float2(fmaxf(med.x + b.x, 0.0f), fmaxf(med.y + b.y, 0.0f));
    ((float2*)g_h1)[(size_t)n * (D_HID / 2) + d2] = r;
}

// ---------------------------------------------------------------------------
// Layer-2 median + bias: 4 nodes/block, 32 threads/node, 2 feat/thread.
// ---------------------------------------------------------------------------
__global__ __launch_bounds__(128)
void median_f2_out(const int* __restrict__ nb, const float* __restrict__ bias,
                   float* __restrict__ out) {
    const int local = threadIdx.x >> 5;               // 0..3
    const int n  = blockIdx.x * 4 + local;
    const int d2 = threadIdx.x & 31;

    __shared__ int sidx[4 * K_NB];
    if (threadIdx.x < 4 * K_NB)
        sidx[threadIdx.x] = nb[(size_t)(blockIdx.x * 4) * K_NB + threadIdx.x];
    __syncthreads();

    const float2* gp = (const float2*)g_g;
    float2 v[K_NB];
#pragma unroll
    for (int k = 0; k < K_NB; ++k)
        v[k] = __ldg(&gp[(size_t)sidx[local * K_NB + k] * (D_OUT / 2) + d2]);

    float2 med = median32_f2(v);
    float2 b = ((const float2*)bias)[d2];
    ((float2*)out)[(size_t)n * (D_OUT / 2) + d2] =
        make_float2(med.x + b.x, med.y + b.y);
}

// ---------------------------------------------------------------------------
extern "C" void kernel_launch(void* const* d_in, const int* in_sizes, int n_in,
                              void* d_out, int out_size) {
    const float* feat = (const float*)d_in[0];
    const float* W1   = (const float*)d_in[1];
    const float* b1   = (const float*)d_in[2];
    const float* W2   = (const float*)d_in[3];
    const float* b2   = (const float*)d_in[4];
    const int*   nb   = (const int*)d_in[5];
    float* out = (float*)d_out;

    void *ph = nullptr, *ph1 = nullptr, *pg = nullptr;
    cudaGetSymbolAddress(&ph,  g_h);
    cudaGetSymbolAddress(&ph1, g_h1);
    cudaGetSymbolAddress(&pg,  g_g);
    float* h  = (float*)ph;
    float* h1 = (float*)ph1;
    float* g  = (float*)pg;

    // 1) h = feat @ W1   (bf16-split tensor cores, register-prefetch pipeline)
    gemm1_bf16<<<M_PAD / 128, 256>>>(feat, W1, h, N_NODES);

    // 2) h1 = relu(median_k h[nb] + b1)
    median_relu_f2<<<N_NODES / 2, 128>>>(nb, b1);

    // 3) g = h1 @ W2
    {
        constexpr int BM = 128, BN = 64, BK = 16, TM = 8, TN = 8;
        dim3 grid((N_NODES + BM - 1) / BM);
        gemm_ffma<BM, BN, BK, TM, TN>
            <<<grid, (BM / TM) * (BN / TN)>>>(h1, W2, g, N_NODES, D_OUT, D_HID);
    }

    // 4) out = median_k g[nb] + b2
    median_f2_out<<<N_NODES / 4, 128>>>(nb, b2, out);
}

// round 8
// speedup vs baseline: 1.7746x; 1.0778x over previous
#include <cuda_runtime.h>
#include <cuda_bf16.h>
#include <mma.h>
#include <cstddef>

using namespace nvcuda;

// Problem constants
#define N_NODES 50000
#define K_NB    32
#define D_IN    512
#define D_HID   128
#define D_OUT   64

#define M_PAD   50048   // 391 * 128: wmma GEMMs store/load unguarded

// Scratch (device globals: allocation-free, graph-capturable, zero-init)
__device__ float g_h [(size_t)M_PAD * D_HID];   // feat@W1 (no bias)
__device__ float g_h1[(size_t)M_PAD * D_HID];   // relu(median + b1), pad rows stay 0
__device__ float g_g [(size_t)M_PAD * D_OUT];   // h1@W2 (no bias)

// ---------------------------------------------------------------------------
// Generic bf16-split GEMM: C[M,N] = A[M,K] @ B[K,N]
// Terms: hi*hi + hi*lo + lo*hi  (lo*lo dropped, ~2^-16 relative)
// 128-row tile, 256 threads (8 warps, 4x2), BK=32, register-prefetch pipeline.
// ---------------------------------------------------------------------------
__device__ __forceinline__ void split_bf16(float x, __nv_bfloat16& hi, __nv_bfloat16& lo) {
    hi = __float2bfloat16_rn(x);
    lo = __float2bfloat16_rn(x - __bfloat162float(hi));
}

__device__ __forceinline__ void store_split4(__nv_bfloat16* hi_base, __nv_bfloat16* lo_base,
                                             int off, float4 v) {
    __nv_bfloat16 h0,h1,h2,h3, l0,l1,l2,l3;
    split_bf16(v.x, h0, l0); split_bf16(v.y, h1, l1);
    split_bf16(v.z, h2, l2); split_bf16(v.w, h3, l3);
    *(__nv_bfloat162*)&hi_base[off]     = __nv_bfloat162(h0, h1);
    *(__nv_bfloat162*)&hi_base[off + 2] = __nv_bfloat162(h2, h3);
    *(__nv_bfloat162*)&lo_base[off]     = __nv_bfloat162(l0, l1);
    *(__nv_bfloat162*)&lo_base[off + 2] = __nv_bfloat162(l2, l3);
}

template<int N_DIM, int K_DIM>
__global__ __launch_bounds__(256)
void gemm_bf16s(const float* __restrict__ A, const float* __restrict__ B,
                float* __restrict__ C, int M) {
    constexpr int BK  = 32;
    constexpr int LDA = BK + 8;        // 40 bf16 row stride
    constexpr int LDB = N_DIM + 8;     // padded row stride
    constexpr int TPR = N_DIM / 4;     // threads per B row (float4 lanes)
    constexpr int RPP = 256 / TPR;     // B rows per pass
    constexpr int PB  = BK / RPP;      // B passes
    constexpr int JF  = N_DIM / 32;    // 16-col frags per warp n-strip
    constexpr int T   = K_DIM / BK;    // k-tiles

    __shared__ __nv_bfloat16 As_hi[128 * LDA], As_lo[128 * LDA];
    __shared__ __nv_bfloat16 Bs_hi[BK * LDB],  Bs_lo[BK * LDB];

    const int tid    = threadIdx.x;
    const int wid    = tid >> 5;
    const int warp_m = wid >> 1;            // 0..3 -> 32-row strip
    const int warp_n = wid & 1;             // 0..1 -> N_DIM/2-col strip
    const int row0   = blockIdx.x * 128;

    const int ar  = tid >> 3;               // A: 8 thr/row, rows ar + p*32
    const int ac4 = (tid & 7) * 4;
    const int br  = tid / TPR;              // B: rows br + p*RPP
    const int bc4 = (tid % TPR) * 4;

    wmma::fragment<wmma::accumulator, 16, 16, 16, float> acc[2][JF];
#pragma unroll
    for (int i = 0; i < 2; ++i)
#pragma unroll
        for (int j = 0; j < JF; ++j) wmma::fill_fragment(acc[i][j], 0.0f);

    float4 pa[4], pb[PB];

    // Prologue: load k-tile 0 into registers
#pragma unroll
    for (int p = 0; p < 4; ++p) {
        int row = ar + p * 32;
        pa[p] = make_float4(0.f, 0.f, 0.f, 0.f);
        if (row0 + row < M)
            pa[p] = *(const float4*)&A[(size_t)(row0 + row) * K_DIM + ac4];
    }
#pragma unroll
    for (int p = 0; p < PB; ++p)
        pb[p] = *(const float4*)&B[(size_t)(br + p * RPP) * N_DIM + bc4];

    for (int t = 0; t < T; ++t) {
        // Store prefetched tile to smem (fp32 -> bf16 hi/lo)
#pragma unroll
        for (int p = 0; p < 4; ++p)
            store_split4(As_hi, As_lo, (ar + p * 32) * LDA + ac4, pa[p]);
#pragma unroll
        for (int p = 0; p < PB; ++p)
            store_split4(Bs_hi, Bs_lo, (br + p * RPP) * LDB + bc4, pb[p]);
        __syncthreads();

        // Prefetch next tile (hidden behind MMA compute)
        if (t + 1 < T) {
            int k0 = (t + 1) * BK;
#pragma unroll
            for (int p = 0; p < 4; ++p) {
                int row = ar + p * 32;
                pa[p] = make_float4(0.f, 0.f, 0.f, 0.f);
                if (row0 + row < M)
                    pa[p] = *(const float4*)&A[(size_t)(row0 + row) * K_DIM + k0 + ac4];
            }
#pragma unroll
            for (int p = 0; p < PB; ++p)
                pb[p] = *(const float4*)&B[(size_t)(k0 + br + p * RPP) * N_DIM + bc4];
        }

        // Compute on current smem tile
#pragma unroll
        for (int kk = 0; kk < 2; ++kk) {
            wmma::fragment<wmma::matrix_b, 16, 16, 16,
                           __nv_bfloat16, wmma::row_major> bh[JF], bl[JF];
#pragma unroll
            for (int j = 0; j < JF; ++j) {
                wmma::load_matrix_sync(bh[j], &Bs_hi[(kk * 16) * LDB + warp_n * (N_DIM / 2) + j * 16], LDB);
                wmma::load_matrix_sync(bl[j], &Bs_lo[(kk * 16) * LDB + warp_n * (N_DIM / 2) + j * 16], LDB);
            }
#pragma unroll
            for (int i = 0; i < 2; ++i) {
                wmma::fragment<wmma::matrix_a, 16, 16, 16,
                               __nv_bfloat16, wmma::row_major> ah, al;
                wmma::load_matrix_sync(ah, &As_hi[(warp_m * 32 + i * 16) * LDA + kk * 16], LDA);
                wmma::load_matrix_sync(al, &As_lo[(warp_m * 32 + i * 16) * LDA + kk * 16], LDA);
#pragma unroll
                for (int j = 0; j < JF; ++j) {
                    wmma::mma_sync(acc[i][j], ah, bh[j], acc[i][j]);
                    wmma::mma_sync(acc[i][j], ah, bl[j], acc[i][j]);
                    wmma::mma_sync(acc[i][j], al, bh[j], acc[i][j]);
                }
            }
        }
        __syncthreads();
    }

    // Store (C padded to M_PAD rows -> unguarded)
#pragma unroll
    for (int i = 0; i < 2; ++i)
#pragma unroll
        for (int j = 0; j < JF; ++j) {
            int r = row0 + warp_m * 32 + i * 16;
            int c = warp_n * (N_DIM / 2) + j * 16;
            wmma::store_matrix_sync(&C[(size_t)r * N_DIM + c], acc[i][j],
                                    N_DIM, wmma::mem_row_major);
        }
}

// ---------------------------------------------------------------------------
// Batcher odd-even merge sort on float2 lanes (two independent medians).
// ---------------------------------------------------------------------------
template<int I, int J>
__device__ __forceinline__ void cmpswap2(float2* v) {
    float ax = v[I].x, bx = v[J].x;
    float ay = v[I].y, by = v[J].y;
    v[I].x = fminf(ax, bx); v[J].x = fmaxf(ax, bx);
    v[I].y = fminf(ay, by); v[J].y = fmaxf(ay, by);
}

template<int I, int END, int STEP, int R>
__device__ __forceinline__ void oem_cloop(float2* v) {
    if constexpr (I + R < END) {
        cmpswap2<I, I + R>(v);
        oem_cloop<I + STEP, END, STEP, R>(v);
    }
}

template<int LO, int N, int R>
__device__ __forceinline__ void oem_merge(float2* v) {
    constexpr int M = R * 2;
    if constexpr (M < N) {
        oem_merge<LO, N, M>(v);
        oem_merge<LO + R, N, M>(v);
        oem_cloop<LO + R, LO + N, M, R>(v);
    } else {
        cmpswap2<LO, LO + R>(v);
    }
}

template<int LO, int N>
__device__ __forceinline__ void oem_sort(float2* v) {
    if constexpr (N > 1) {
        constexpr int M = N / 2;
        oem_sort<LO, M>(v);
        oem_sort<LO + M, M>(v);
        oem_merge<LO, N, 1>(v);
    }
}

// Lower median (rank 15) of 32, on both float2 lanes.
__device__ __forceinline__ float2 median32_f2(float2* v) {
    oem_sort<0, 16>(v);
    oem_sort<0, 16>(v + 16);
    float mx = fminf(v[0].x, v[31].x);
    float my = fminf(v[0].y, v[31].y);
#pragma unroll
    for (int i = 1; i < 16; ++i) {
        mx = fmaxf(mx, fminf(v[i].x, v[31 - i].x));
        my = fmaxf(my, fminf(v[i].y, v[31 - i].y));
    }
    return make_float2(mx, my);
}

// ---------------------------------------------------------------------------
// Layer-1 median + bias + ReLU: 2 nodes/block, 64 threads/node, 2 feat/thread.
// ---------------------------------------------------------------------------
__global__ __launch_bounds__(128)
void median_relu_f2(const int* __restrict__ nb, const float* __restrict__ bias) {
    const int local = threadIdx.x >> 6;
    const int n  = blockIdx.x * 2 + local;
    const int d2 = threadIdx.x & 63;

    __shared__ int sidx[2 * K_NB];
    if (threadIdx.x < 2 * K_NB)
        sidx[threadIdx.x] = nb[(size_t)(blockIdx.x * 2) * K_NB + threadIdx.x];
    __syncthreads();

    const float2* hp = (const float2*)g_h;
    float2 v[K_NB];
#pragma unroll
    for (int k = 0; k < K_NB; ++k)
        v[k] = __ldg(&hp[(size_t)sidx[local * K_NB + k] * (D_HID / 2) + d2]);

    float2 med = median32_f2(v);
    float2 b = ((const float2*)bias)[d2];
    float2 r = make_float2(fmaxf(med.x + b.x, 0.0f), fmaxf(med.y + b.y, 0.0f));
    ((float2*)g_h1)[(size_t)n * (D_HID / 2) + d2] = r;
}

// ---------------------------------------------------------------------------
// Layer-2 median + bias: 4 nodes/block, 32 threads/node, 2 feat/thread.
// ---------------------------------------------------------------------------
__global__ __launch_bounds__(128)
void median_f2_out(const int* __restrict__ nb, const float* __restrict__ bias,
                   float* __restrict__ out) {
    const int local = threadIdx.x >> 5;
    const int n  = blockIdx.x * 4 + local;
    const int d2 = threadIdx.x & 31;

    __shared__ int sidx[4 * K_NB];
    if (threadIdx.x < 4 * K_NB)
        sidx[threadIdx.x] = nb[(size_t)(blockIdx.x * 4) * K_NB + threadIdx.x];
    __syncthreads();

    const float2* gp = (const float2*)g_g;
    float2 v[K_NB];
#pragma unroll
    for (int k = 0; k < K_NB; ++k)
        v[k] = __ldg(&gp[(size_t)sidx[local * K_NB + k] * (D_OUT / 2) + d2]);

    float2 med = median32_f2(v);
    float2 b = ((const float2*)bias)[d2];
    ((float2*)out)[(size_t)n * (D_OUT / 2) + d2] =
        make_float2(med.x + b.x, med.y + b.y);
}

// ---------------------------------------------------------------------------
extern "C" void kernel_launch(void* const* d_in, const int* in_sizes, int n_in,
                              void* d_out, int out_size) {
    const float* feat = (const float*)d_in[0];
    const float* W1   = (const float*)d_in[1];
    const float* b1   = (const float*)d_in[2];
    const float* W2   = (const float*)d_in[3];
    const float* b2   = (const float*)d_in[4];
    const int*   nb   = (const int*)d_in[5];
    float* out = (float*)d_out;

    void *ph = nullptr, *ph1 = nullptr, *pg = nullptr;
    cudaGetSymbolAddress(&ph,  g_h);
    cudaGetSymbolAddress(&ph1, g_h1);
    cudaGetSymbolAddress(&pg,  g_g);
    float* h  = (float*)ph;
    float* h1 = (float*)ph1;
    float* g  = (float*)pg;

    // 1) h = feat @ W1   [50000,512]x[512,128]  (bf16-split wmma)
    gemm_bf16s<D_HID, D_IN><<<M_PAD / 128, 256>>>(feat, W1, h, N_NODES);

    // 2) h1 = relu(median_k h[nb] + b1)
    median_relu_f2<<<N_NODES / 2, 128>>>(nb, b1);

    // 3) g = h1 @ W2   [50048,128]x[128,64]  (bf16-split wmma, pad rows are 0)
    gemm_bf16s<D_OUT, D_HID><<<M_PAD / 128, 256>>>(h1, W2, g, M_PAD);

    // 4) out = median_k g[nb] + b2
    median_f2_out<<<N_NODES / 4, 128>>>(nb, b2, out);
}

// round 9
// speedup vs baseline: 1.8074x; 1.0185x over previous
#include <cuda_runtime.h>
#include <cuda_bf16.h>
#include <mma.h>
#include <cstddef>

using namespace nvcuda;

// Problem constants
#define N_NODES 50000
#define K_NB    32
#define D_IN    512
#define D_HID   128
#define D_OUT   64

#define M_PAD   50048   // 391 * 128: wmma GEMMs store/load unguarded

// Scratch (device globals: allocation-free, graph-capturable, zero-init)
__device__ float g_h [(size_t)M_PAD * D_HID];   // feat@W1 (no bias)
__device__ float g_h1[(size_t)M_PAD * D_HID];   // relu(median + b1), pad rows stay 0
__device__ float g_g [(size_t)M_PAD * D_OUT];   // h1@W2 (no bias)

// ---------------------------------------------------------------------------
// Generic bf16-split GEMM: C[M,N] = A[M,K] @ B[K,N]
// Terms: hi*hi + hi*lo + lo*hi  (lo*lo dropped, ~2^-16 relative)
// 128-row tile, 256 threads (8 warps, 4x2), BK=32, register-prefetch pipeline.
// ---------------------------------------------------------------------------
__device__ __forceinline__ void split_bf16(float x, __nv_bfloat16& hi, __nv_bfloat16& lo) {
    hi = __float2bfloat16_rn(x);
    lo = __float2bfloat16_rn(x - __bfloat162float(hi));
}

__device__ __forceinline__ void store_split4(__nv_bfloat16* hi_base, __nv_bfloat16* lo_base,
                                             int off, float4 v) {
    __nv_bfloat16 h0,h1,h2,h3, l0,l1,l2,l3;
    split_bf16(v.x, h0, l0); split_bf16(v.y, h1, l1);
    split_bf16(v.z, h2, l2); split_bf16(v.w, h3, l3);
    *(__nv_bfloat162*)&hi_base[off]     = __nv_bfloat162(h0, h1);
    *(__nv_bfloat162*)&hi_base[off + 2] = __nv_bfloat162(h2, h3);
    *(__nv_bfloat162*)&lo_base[off]     = __nv_bfloat162(l0, l1);
    *(__nv_bfloat162*)&lo_base[off + 2] = __nv_bfloat162(l2, l3);
}

template<int N_DIM, int K_DIM>
__global__ __launch_bounds__(256)
void gemm_bf16s(const float* __restrict__ A, const float* __restrict__ B,
                float* __restrict__ C, int M) {
    constexpr int BK  = 32;
    constexpr int LDA = BK + 8;
    constexpr int LDB = N_DIM + 8;
    constexpr int TPR = N_DIM / 4;
    constexpr int RPP = 256 / TPR;
    constexpr int PB  = BK / RPP;
    constexpr int JF  = N_DIM / 32;
    constexpr int T   = K_DIM / BK;

    __shared__ __nv_bfloat16 As_hi[128 * LDA], As_lo[128 * LDA];
    __shared__ __nv_bfloat16 Bs_hi[BK * LDB],  Bs_lo[BK * LDB];

    const int tid    = threadIdx.x;
    const int wid    = tid >> 5;
    const int warp_m = wid >> 1;
    const int warp_n = wid & 1;
    const int row0   = blockIdx.x * 128;

    const int ar  = tid >> 3;
    const int ac4 = (tid & 7) * 4;
    const int br  = tid / TPR;
    const int bc4 = (tid % TPR) * 4;

    wmma::fragment<wmma::accumulator, 16, 16, 16, float> acc[2][JF];
#pragma unroll
    for (int i = 0; i < 2; ++i)
#pragma unroll
        for (int j = 0; j < JF; ++j) wmma::fill_fragment(acc[i][j], 0.0f);

    float4 pa[4], pb[PB];

#pragma unroll
    for (int p = 0; p < 4; ++p) {
        int row = ar + p * 32;
        pa[p] = make_float4(0.f, 0.f, 0.f, 0.f);
        if (row0 + row < M)
            pa[p] = *(const float4*)&A[(size_t)(row0 + row) * K_DIM + ac4];
    }
#pragma unroll
    for (int p = 0; p < PB; ++p)
        pb[p] = *(const float4*)&B[(size_t)(br + p * RPP) * N_DIM + bc4];

    for (int t = 0; t < T; ++t) {
#pragma unroll
        for (int p = 0; p < 4; ++p)
            store_split4(As_hi, As_lo, (ar + p * 32) * LDA + ac4, pa[p]);
#pragma unroll
        for (int p = 0; p < PB; ++p)
            store_split4(Bs_hi, Bs_lo, (br + p * RPP) * LDB + bc4, pb[p]);
        __syncthreads();

        if (t + 1 < T) {
            int k0 = (t + 1) * BK;
#pragma unroll
            for (int p = 0; p < 4; ++p) {
                int row = ar + p * 32;
                pa[p] = make_float4(0.f, 0.f, 0.f, 0.f);
                if (row0 + row < M)
                    pa[p] = *(const float4*)&A[(size_t)(row0 + row) * K_DIM + k0 + ac4];
            }
#pragma unroll
            for (int p = 0; p < PB; ++p)
                pb[p] = *(const float4*)&B[(size_t)(k0 + br + p * RPP) * N_DIM + bc4];
        }

#pragma unroll
        for (int kk = 0; kk < 2; ++kk) {
            wmma::fragment<wmma::matrix_b, 16, 16, 16,
                           __nv_bfloat16, wmma::row_major> bh[JF], bl[JF];
#pragma unroll
            for (int j = 0; j < JF; ++j) {
                wmma::load_matrix_sync(bh[j], &Bs_hi[(kk * 16) * LDB + warp_n * (N_DIM / 2) + j * 16], LDB);
                wmma::load_matrix_sync(bl[j], &Bs_lo[(kk * 16) * LDB + warp_n * (N_DIM / 2) + j * 16], LDB);
            }
#pragma unroll
            for (int i = 0; i < 2; ++i) {
                wmma::fragment<wmma::matrix_a, 16, 16, 16,
                               __nv_bfloat16, wmma::row_major> ah, al;
                wmma::load_matrix_sync(ah, &As_hi[(warp_m * 32 + i * 16) * LDA + kk * 16], LDA);
                wmma::load_matrix_sync(al, &As_lo[(warp_m * 32 + i * 16) * LDA + kk * 16], LDA);
#pragma unroll
                for (int j = 0; j < JF; ++j) {
                    wmma::mma_sync(acc[i][j], ah, bh[j], acc[i][j]);
                    wmma::mma_sync(acc[i][j], ah, bl[j], acc[i][j]);
                    wmma::mma_sync(acc[i][j], al, bh[j], acc[i][j]);
                }
            }
        }
        __syncthreads();
    }

#pragma unroll
    for (int i = 0; i < 2; ++i)
#pragma unroll
        for (int j = 0; j < JF; ++j) {
            int r = row0 + warp_m * 32 + i * 16;
            int c = warp_n * (N_DIM / 2) + j * 16;
            wmma::store_matrix_sync(&C[(size_t)r * N_DIM + c], acc[i][j],
                                    N_DIM, wmma::mem_row_major);
        }
}

// ---------------------------------------------------------------------------
// Batcher odd-even merge sort on float2 lanes, DUAL-PIPE comparators:
// ~6/19 of comparators use FMA-pipe arithmetic (s,d,lo=(s-|d|)/2, hi=s-lo),
// the rest use ALU-pipe FMNMX. Balances alu/fma pipes + issue slots.
// ---------------------------------------------------------------------------
template<int I, int J>
__device__ __forceinline__ void cmpswap2(float2* v) {
    constexpr bool USE_FMA = (((I * 37 + J * 11) % 19) < 6);
    if constexpr (USE_FMA) {
        float sx = v[I].x + v[J].x, dx = v[I].x - v[J].x;
        float sy = v[I].y + v[J].y, dy = v[I].y - v[J].y;
        float lx = (sx - fabsf(dx)) * 0.5f;
        float ly = (sy - fabsf(dy)) * 0.5f;
        v[I].x = lx; v[J].x = sx - lx;
        v[I].y = ly; v[J].y = sy - ly;
    } else {
        float ax = v[I].x, bx = v[J].x;
        float ay = v[I].y, by = v[J].y;
        v[I].x = fminf(ax, bx); v[J].x = fmaxf(ax, bx);
        v[I].y = fminf(ay, by); v[J].y = fmaxf(ay, by);
    }
}

template<int I, int END, int STEP, int R>
__device__ __forceinline__ void oem_cloop(float2* v) {
    if constexpr (I + R < END) {
        cmpswap2<I, I + R>(v);
        oem_cloop<I + STEP, END, STEP, R>(v);
    }
}

template<int LO, int N, int R>
__device__ __forceinline__ void oem_merge(float2* v) {
    constexpr int M = R * 2;
    if constexpr (M < N) {
        oem_merge<LO, N, M>(v);
        oem_merge<LO + R, N, M>(v);
        oem_cloop<LO + R, LO + N, M, R>(v);
    } else {
        cmpswap2<LO, LO + R>(v);
    }
}

template<int LO, int N>
__device__ __forceinline__ void oem_sort(float2* v) {
    if constexpr (N > 1) {
        constexpr int M = N / 2;
        oem_sort<LO, M>(v);
        oem_sort<LO + M, M>(v);
        oem_merge<LO, N, 1>(v);
    }
}

// Lower median (rank 15) of 32, on both float2 lanes.
__device__ __forceinline__ float2 median32_f2(float2* v) {
    oem_sort<0, 16>(v);
    oem_sort<0, 16>(v + 16);
    float mx = fminf(v[0].x, v[31].x);
    float my = fminf(v[0].y, v[31].y);
#pragma unroll
    for (int i = 1; i < 16; ++i) {
        mx = fmaxf(mx, fminf(v[i].x, v[31 - i].x));
        my = fmaxf(my, fminf(v[i].y, v[31 - i].y));
    }
    return make_float2(mx, my);
}

// ---------------------------------------------------------------------------
// Layer-1 median + bias + ReLU: 2 nodes/block, 64 threads/node, 2 feat/thread.
// ---------------------------------------------------------------------------
__global__ __launch_bounds__(128)
void median_relu_f2(const int* __restrict__ nb, const float* __restrict__ bias) {
    const int local = threadIdx.x >> 6;
    const int n  = blockIdx.x * 2 + local;
    const int d2 = threadIdx.x & 63;

    __shared__ int sidx[2 * K_NB];
    if (threadIdx.x < 2 * K_NB)
        sidx[threadIdx.x] = nb[(size_t)(blockIdx.x * 2) * K_NB + threadIdx.x];
    __syncthreads();

    const float2* hp = (const float2*)g_h;
    float2 v[K_NB];
#pragma unroll
    for (int k = 0; k < K_NB; ++k)
        v[k] = __ldg(&hp[(size_t)sidx[local * K_NB + k] * (D_HID / 2) + d2]);

    float2 med = median32_f2(v);
    float2 b = ((const float2*)bias)[d2];
    float2 r = make_float2(fmaxf(med.x + b.x, 0.0f), fmaxf(med.y + b.y, 0.0f));
    ((float2*)g_h1)[(size_t)n * (D_HID / 2) + d2] = r;
}

// ---------------------------------------------------------------------------
// Layer-2 median + bias: 4 nodes/block, 32 threads/node, 2 feat/thread.
// ---------------------------------------------------------------------------
__global__ __launch_bounds__(128)
void median_f2_out(const int* __restrict__ nb, const float* __restrict__ bias,
                   float* __restrict__ out) {
    const int local = threadIdx.x >> 5;
    const int n  = blockIdx.x * 4 + local;
    const int d2 = threadIdx.x & 31;

    __shared__ int sidx[4 * K_NB];
    if (threadIdx.x < 4 * K_NB)
        sidx[threadIdx.x] = nb[(size_t)(blockIdx.x * 4) * K_NB + threadIdx.x];
    __syncthreads();

    const float2* gp = (const float2*)g_g;
    float2 v[K_NB];
#pragma unroll
    for (int k = 0; k < K_NB; ++k)
        v[k] = __ldg(&gp[(size_t)sidx[local * K_NB + k] * (D_OUT / 2) + d2]);

    float2 med = median32_f2(v);
    float2 b = ((const float2*)bias)[d2];
    ((float2*)out)[(size_t)n * (D_OUT / 2) + d2] =
        make_float2(med.x + b.x, med.y + b.y);
}

// ---------------------------------------------------------------------------
extern "C" void kernel_launch(void* const* d_in, const int* in_sizes, int n_in,
                              void* d_out, int out_size) {
    const float* feat = (const float*)d_in[0];
    const float* W1   = (const float*)d_in[1];
    const float* b1   = (const float*)d_in[2];
    const float* W2   = (const float*)d_in[3];
    const float* b2   = (const float*)d_in[4];
    const int*   nb   = (const int*)d_in[5];
    float* out = (float*)d_out;

    void *ph = nullptr, *ph1 = nullptr, *pg = nullptr;
    cudaGetSymbolAddress(&ph,  g_h);
    cudaGetSymbolAddress(&ph1, g_h1);
    cudaGetSymbolAddress(&pg,  g_g);
    float* h  = (float*)ph;
    float* h1 = (float*)ph1;
    float* g  = (float*)pg;

    // 1) h = feat @ W1   [50000,512]x[512,128]  (bf16-split wmma)
    gemm_bf16s<D_HID, D_IN><<<M_PAD / 128, 256>>>(feat, W1, h, N_NODES);

    // 2) h1 = relu(median_k h[nb] + b1)
    median_relu_f2<<<N_NODES / 2, 128>>>(nb, b1);

    // 3) g = h1 @ W2   [50048,128]x[128,64]  (bf16-split wmma, pad rows are 0)
    gemm_bf16s<D_OUT, D_HID><<<M_PAD / 128, 256>>>(h1, W2, g, M_PAD);

    // 4) out = median_k g[nb] + b2
    median_f2_out<<<N_NODES / 4, 128>>>(nb, b2, out);
}